// round 15
// baseline (speedup 1.0000x reference)
#include <cuda_runtime.h>
#include <cuda_fp16.h>
#include <stdint.h>

#define Bsz 8
#define H   12
#define Nq  1024
#define Dh  64
#define SCALE 0.125f
#define EPS 1e-6f

#define BM 128
#define BN 128            // staged key-tile (two 64-key halves per barrier)
#define NT 256
#define NTILES (Nq / BN)  // 8
#define RPITCH 144        // bytes per smem row (72 halves: 64 data + 8 pad)

// smem byte offsets: all tiles 128 rows x 144 B = 18432 B
#define SM_Q  0
#define SM_K0 18432
#define SM_K1 36864
#define SM_V0 55296
#define SM_V1 73728
#define SMEM_BYTES 92160

__device__ __forceinline__ uint32_t s2u(const void* p) {
    uint32_t a;
    asm("{ .reg .u64 t; cvta.to.shared.u64 t, %1; cvt.u32.u64 %0, t; }" : "=r"(a) : "l"(p));
    return a;
}
__device__ __forceinline__ uint32_t ph2(float lo, float hi) {
    __half2 h = __floats2half2_rn(lo, hi);
    return *(uint32_t*)&h;
}
__device__ __forceinline__ void ldm_x4(uint32_t r[4], uint32_t addr) {
    asm volatile("ldmatrix.sync.aligned.m8n8.x4.shared.b16 {%0,%1,%2,%3}, [%4];"
                 : "=r"(r[0]), "=r"(r[1]), "=r"(r[2]), "=r"(r[3]) : "r"(addr));
}
__device__ __forceinline__ void ldm_x4t(uint32_t r[4], uint32_t addr) {
    asm volatile("ldmatrix.sync.aligned.m8n8.x4.trans.shared.b16 {%0,%1,%2,%3}, [%4];"
                 : "=r"(r[0]), "=r"(r[1]), "=r"(r[2]), "=r"(r[3]) : "r"(addr));
}
__device__ __forceinline__ void mma16(float c[4], const uint32_t a[4],
                                      uint32_t b0, uint32_t b1) {
    asm volatile(
        "mma.sync.aligned.m16n8k16.row.col.f32.f16.f16.f32 "
        "{%0,%1,%2,%3},{%4,%5,%6,%7},{%8,%9},{%0,%1,%2,%3};\n"
        : "+f"(c[0]), "+f"(c[1]), "+f"(c[2]), "+f"(c[3])
        : "r"(a[0]), "r"(a[1]), "r"(a[2]), "r"(a[3]), "r"(b0), "r"(b1));
}

__global__ __launch_bounds__(NT, 2) void l2q_h10_kernel(
    const float* __restrict__ q, const float* __restrict__ k,
    const float* __restrict__ v, const float* __restrict__ alpha,
    const float* __restrict__ beta, const float* __restrict__ gamma,
    float* __restrict__ out)
{
    extern __shared__ char smc[];
    const uint32_t sb = s2u(smc);

    const int tid  = threadIdx.x;
    const int w    = tid >> 5;    // warp 0..7 -> rows w*16..w*16+15
    const int lane = tid & 31;
    const int g    = lane >> 2;
    const int t    = lane & 3;

    const int bh = blockIdx.y;
    const int h  = bh % H;
    const int m0 = blockIdx.x * BM;

    const float* qb = q + (size_t)bh * Nq * Dh;
    const float* kb = k + (size_t)bh * Nq * Dh;
    const float* vb = v + (size_t)bh * Nq * Dh;
    float*       ob = out + (size_t)bh * Nq * Dh;

    const float a2c = alpha[h] * SCALE * SCALE;
    const float b1c = beta[h] * SCALE;
    const float g0c = gamma[h];

    // ldmatrix lane-address offsets (r4-verified layouts)
    const uint32_t qaddr = sb + SM_Q + (uint32_t)(w * 16 + (lane & 15)) * RPITCH
                         + (uint32_t)((lane >> 4) << 4);
    const uint32_t krow_off = (uint32_t)((lane & 7) + ((lane >> 4) << 3)) * RPITCH
                            + (uint32_t)(((lane >> 3) & 1) << 4);
    const uint32_t vrow_off = (uint32_t)((lane & 7) + (((lane >> 3) & 1) << 3)) * RPITCH
                            + (uint32_t)((lane >> 4) << 4);

    // staging: thread owns float4-column cc of rows rbase+16j
    const int rbase = tid >> 4;   // 0..15
    const int cc    = tid & 15;

    // ---- stage Q (fp32 -> fp16, once) ----
    #pragma unroll
    for (int j = 0; j < 8; j++) {
        int row = rbase + 16 * j;
        float4 f = *(const float4*)(qb + (size_t)(m0 + row) * Dh + cc * 4);
        *(uint2*)(smc + SM_Q + row * RPITCH + cc * 8) =
            make_uint2(ph2(f.x, f.y), ph2(f.z, f.w));
    }
    // ---- stage K/V tile 0 (128 rows each) ----
    #pragma unroll
    for (int j = 0; j < 8; j++) {
        int row = rbase + 16 * j;
        float4 fk = *(const float4*)(kb + (size_t)row * Dh + cc * 4);
        float4 fv = *(const float4*)(vb + (size_t)row * Dh + cc * 4);
        *(uint2*)(smc + SM_K0 + row * RPITCH + cc * 8) =
            make_uint2(ph2(fk.x, fk.y), ph2(fk.z, fk.w));
        *(uint2*)(smc + SM_V0 + row * RPITCH + cc * 8) =
            make_uint2(ph2(fv.x, fv.y), ph2(fv.z, fv.w));
    }
    __syncthreads();

    float o[8][4];
    #pragma unroll
    for (int d = 0; d < 8; d++)
        #pragma unroll
        for (int r = 0; r < 4; r++) o[d][r] = 0.f;
    float rs0 = 0.f, rs1 = 0.f;

    for (int tt = 0; tt < NTILES; tt++) {
        const uint32_t kbase = sb + ((tt & 1) ? SM_K1 : SM_K0);
        const uint32_t vbase = sb + ((tt & 1) ? SM_V1 : SM_V0);
        char* kd = smc + ((tt & 1) ? SM_K0 : SM_K1);
        char* vd = smc + ((tt & 1) ? SM_V0 : SM_V1);
        const bool pf = (tt < NTILES - 1);
        const size_t nb = (size_t)(tt + 1) * BN;

        uint32_t ap[4][4];
        float c[8][4];

        // ---- prefetch next-K batch A (rows 0-63, 16 regs) ----
        float4 kfA[4];
        if (pf) {
            #pragma unroll
            for (int j = 0; j < 4; j++)
                kfA[j] = *(const float4*)(kb + (nb + rbase + 16 * j) * Dh + cc * 4);
        }

        // ==================== half 0 (keys 0-63 of tile) ====================
        #pragma unroll
        for (int nf = 0; nf < 8; nf++)
            #pragma unroll
            for (int r = 0; r < 4; r++) c[nf][r] = 0.f;

        #pragma unroll
        for (int ks = 0; ks < 4; ks++) {
            uint32_t a[4];
            ldm_x4(a, qaddr + ks * 32);
            #pragma unroll
            for (int p = 0; p < 4; p++) {
                uint32_t b[4];
                ldm_x4(b, kbase + p * (16 * RPITCH) + ks * 32 + krow_off);
                mma16(c[2 * p],     a, b[0], b[1]);
                mma16(c[2 * p + 1], a, b[2], b[3]);
            }
        }
        #pragma unroll
        for (int nf = 0; nf < 8; nf++) {
            float p0 = fmaxf(fmaf(fmaf(a2c, c[nf][0], b1c), c[nf][0], g0c), 0.f);
            float p1 = fmaxf(fmaf(fmaf(a2c, c[nf][1], b1c), c[nf][1], g0c), 0.f);
            float p2 = fmaxf(fmaf(fmaf(a2c, c[nf][2], b1c), c[nf][2], g0c), 0.f);
            float p3 = fmaxf(fmaf(fmaf(a2c, c[nf][3], b1c), c[nf][3], g0c), 0.f);
            rs0 += p0 + p1;
            rs1 += p2 + p3;
            ap[nf >> 1][(nf & 1) * 2 + 0] = ph2(p0, p1);
            ap[nf >> 1][(nf & 1) * 2 + 1] = ph2(p2, p3);
        }

        // store kfA, prefetch next-K batch B (rows 64-127)
        float4 kfB[4];
        if (pf) {
            #pragma unroll
            for (int j = 0; j < 4; j++)
                *(uint2*)(kd + (rbase + 16 * j) * RPITCH + cc * 8) =
                    make_uint2(ph2(kfA[j].x, kfA[j].y), ph2(kfA[j].z, kfA[j].w));
            #pragma unroll
            for (int j = 4; j < 8; j++)
                kfB[j - 4] = *(const float4*)(kb + (nb + rbase + 16 * j) * Dh + cc * 4);
        }

        #pragma unroll
        for (int ks2 = 0; ks2 < 4; ks2++) {
            #pragma unroll
            for (int p = 0; p < 4; p++) {
                uint32_t b[4];
                ldm_x4t(b, vbase + ks2 * (16 * RPITCH) + p * 32 + vrow_off);
                mma16(o[2 * p],     ap[ks2], b[0], b[1]);
                mma16(o[2 * p + 1], ap[ks2], b[2], b[3]);
            }
        }

        // store kfB, prefetch next-V batch A
        float4 vfA[4];
        if (pf) {
            #pragma unroll
            for (int j = 4; j < 8; j++)
                *(uint2*)(kd + (rbase + 16 * j) * RPITCH + cc * 8) =
                    make_uint2(ph2(kfB[j - 4].x, kfB[j - 4].y),
                               ph2(kfB[j - 4].z, kfB[j - 4].w));
            #pragma unroll
            for (int j = 0; j < 4; j++)
                vfA[j] = *(const float4*)(vb + (nb + rbase + 16 * j) * Dh + cc * 4);
        }

        // ==================== half 1 (keys 64-127 of tile) ====================
        {
            const uint32_t khalf = kbase + 64 * RPITCH;
            #pragma unroll
            for (int nf = 0; nf < 8; nf++)
                #pragma unroll
                for (int r = 0; r < 4; r++) c[nf][r] = 0.f;

            #pragma unroll
            for (int ks = 0; ks < 4; ks++) {
                uint32_t a[4];
                ldm_x4(a, qaddr + ks * 32);
                #pragma unroll
                for (int p = 0; p < 4; p++) {
                    uint32_t b[4];
                    ldm_x4(b, khalf + p * (16 * RPITCH) + ks * 32 + krow_off);
                    mma16(c[2 * p],     a, b[0], b[1]);
                    mma16(c[2 * p + 1], a, b[2], b[3]);
                }
            }
            #pragma unroll
            for (int nf = 0; nf < 8; nf++) {
                float p0 = fmaxf(fmaf(fmaf(a2c, c[nf][0], b1c), c[nf][0], g0c), 0.f);
                float p1 = fmaxf(fmaf(fmaf(a2c, c[nf][1], b1c), c[nf][1], g0c), 0.f);
                float p2 = fmaxf(fmaf(fmaf(a2c, c[nf][2], b1c), c[nf][2], g0c), 0.f);
                float p3 = fmaxf(fmaf(fmaf(a2c, c[nf][3], b1c), c[nf][3], g0c), 0.f);
                rs0 += p0 + p1;
                rs1 += p2 + p3;
                ap[nf >> 1][(nf & 1) * 2 + 0] = ph2(p0, p1);
                ap[nf >> 1][(nf & 1) * 2 + 1] = ph2(p2, p3);
            }
        }

        // store vfA, prefetch next-V batch B
        float4 vfB[4];
        if (pf) {
            #pragma unroll
            for (int j = 0; j < 4; j++)
                *(uint2*)(vd + (rbase + 16 * j) * RPITCH + cc * 8) =
                    make_uint2(ph2(vfA[j].x, vfA[j].y), ph2(vfA[j].z, vfA[j].w));
            #pragma unroll
            for (int j = 4; j < 8; j++)
                vfB[j - 4] = *(const float4*)(vb + (nb + rbase + 16 * j) * Dh + cc * 4);
        }

        {
            const uint32_t vhalf = vbase + 64 * RPITCH;
            #pragma unroll
            for (int ks2 = 0; ks2 < 4; ks2++) {
                #pragma unroll
                for (int p = 0; p < 4; p++) {
                    uint32_t b[4];
                    ldm_x4t(b, vhalf + ks2 * (16 * RPITCH) + p * 32 + vrow_off);
                    mma16(o[2 * p],     ap[ks2], b[0], b[1]);
                    mma16(o[2 * p + 1], ap[ks2], b[2], b[3]);
                }
            }
        }

        // store vfB, single barrier per 128-key tile
        if (pf) {
            #pragma unroll
            for (int j = 4; j < 8; j++)
                *(uint2*)(vd + (rbase + 16 * j) * RPITCH + cc * 8) =
                    make_uint2(ph2(vfB[j - 4].x, vfB[j - 4].y),
                               ph2(vfB[j - 4].z, vfB[j - 4].w));
            __syncthreads();
        }
    }

    // ---- rowsum closes within warp (4 t-lanes) ----
    rs0 += __shfl_xor_sync(0xFFFFFFFFu, rs0, 1);
    rs0 += __shfl_xor_sync(0xFFFFFFFFu, rs0, 2);
    rs1 += __shfl_xor_sync(0xFFFFFFFFu, rs1, 1);
    rs1 += __shfl_xor_sync(0xFFFFFFFFu, rs1, 2);
    const float inv0 = 1.f / (rs0 + EPS);
    const float inv1 = 1.f / (rs1 + EPS);

    // ---- normalize + store ----
    const int row0 = m0 + w * 16 + g;
    #pragma unroll
    for (int d = 0; d < 8; d++) {
        float2 lo = {o[d][0] * inv0, o[d][1] * inv0};
        float2 hi = {o[d][2] * inv1, o[d][3] * inv1};
        *(float2*)(ob + (size_t)row0 * Dh + d * 8 + 2 * t)       = lo;
        *(float2*)(ob + (size_t)(row0 + 8) * Dh + d * 8 + 2 * t) = hi;
    }
}

extern "C" void kernel_launch(void* const* d_in, const int* in_sizes, int n_in,
                              void* d_out, int out_size)
{
    const float* q     = (const float*)d_in[0];
    const float* k     = (const float*)d_in[1];
    const float* v     = (const float*)d_in[2];
    const float* alpha = (const float*)d_in[3];
    const float* beta  = (const float*)d_in[4];
    const float* gamma = (const float*)d_in[5];
    float* out = (float*)d_out;

    cudaFuncSetAttribute(l2q_h10_kernel,
                         cudaFuncAttributeMaxDynamicSharedMemorySize, SMEM_BYTES);

    dim3 grid(Nq / BM, Bsz * H);
    l2q_h10_kernel<<<grid, NT, SMEM_BYTES>>>(q, k, v, alpha, beta, gamma, out);
}

// round 16
// speedup vs baseline: 1.5196x; 1.5196x over previous
#include <cuda_runtime.h>
#include <cuda_fp16.h>
#include <stdint.h>

#define Bsz 8
#define H   12
#define Nq  1024
#define Dh  64
#define SCALE 0.125f
#define EPS 1e-6f

#define BM 128
#define BN 64
#define NT 256
#define NTILES (Nq / BN)   // 16
#define RPITCH 144          // bytes per smem row (72 halves: 64 data + 8 pad)

// smem byte offsets
#define SM_Q  0                       // 128 rows -> 18432 B
#define SM_K0 18432                   // 64 rows  -> 9216 B
#define SM_K1 (18432 + 9216)
#define SM_V0 36864
#define SM_V1 (36864 + 9216)
#define SMEM_BYTES 55296

__device__ __forceinline__ uint32_t s2u(const void* p) {
    uint32_t a;
    asm("{ .reg .u64 t; cvta.to.shared.u64 t, %1; cvt.u32.u64 %0, t; }" : "=r"(a) : "l"(p));
    return a;
}
__device__ __forceinline__ uint32_t ph2(float lo, float hi) {
    __half2 h = __floats2half2_rn(lo, hi);   // .x = lo, .y = hi
    return *(uint32_t*)&h;
}
__device__ __forceinline__ void ldm_x4(uint32_t r[4], uint32_t addr) {
    asm volatile("ldmatrix.sync.aligned.m8n8.x4.shared.b16 {%0,%1,%2,%3}, [%4];"
                 : "=r"(r[0]), "=r"(r[1]), "=r"(r[2]), "=r"(r[3]) : "r"(addr));
}
__device__ __forceinline__ void ldm_x4t(uint32_t r[4], uint32_t addr) {
    asm volatile("ldmatrix.sync.aligned.m8n8.x4.trans.shared.b16 {%0,%1,%2,%3}, [%4];"
                 : "=r"(r[0]), "=r"(r[1]), "=r"(r[2]), "=r"(r[3]) : "r"(addr));
}
__device__ __forceinline__ void mma16(float c[4], const uint32_t a[4],
                                      uint32_t b0, uint32_t b1) {
    asm volatile(
        "mma.sync.aligned.m16n8k16.row.col.f32.f16.f16.f32 "
        "{%0,%1,%2,%3},{%4,%5,%6,%7},{%8,%9},{%0,%1,%2,%3};\n"
        : "+f"(c[0]), "+f"(c[1]), "+f"(c[2]), "+f"(c[3])
        : "r"(a[0]), "r"(a[1]), "r"(a[2]), "r"(a[3]), "r"(b0), "r"(b1));
}

__global__ __launch_bounds__(NT, 2) void l2q_h2_kernel(
    const float* __restrict__ q, const float* __restrict__ k,
    const float* __restrict__ v, const float* __restrict__ alpha,
    const float* __restrict__ beta, const float* __restrict__ gamma,
    float* __restrict__ out)
{
    extern __shared__ char smc[];
    const uint32_t sb = s2u(smc);

    const int tid  = threadIdx.x;
    const int w    = tid >> 5;    // warp 0..7 -> rows w*16..w*16+15
    const int lane = tid & 31;
    const int g    = lane >> 2;
    const int t    = lane & 3;

    const int bh = blockIdx.y;
    const int h  = bh % H;
    const int m0 = blockIdx.x * BM;

    const float* qb = q + (size_t)bh * Nq * Dh;
    const float* kb = k + (size_t)bh * Nq * Dh;
    const float* vb = v + (size_t)bh * Nq * Dh;
    float*       ob = out + (size_t)bh * Nq * Dh;

    const float a2c = alpha[h] * SCALE * SCALE;
    const float b1c = beta[h] * SCALE;
    const float g0c = gamma[h];

    // ---- per-lane ldmatrix address offsets (r4-verified) ----
    const uint32_t qaddr = sb + SM_Q + (uint32_t)(w * 16 + (lane & 15)) * RPITCH
                         + (uint32_t)((lane >> 4) << 4);
    const uint32_t krow_off = (uint32_t)((lane & 7) + ((lane >> 4) << 3)) * RPITCH
                            + (uint32_t)(((lane >> 3) & 1) << 4);
    const uint32_t vrow_off = (uint32_t)((lane & 7) + (((lane >> 3) & 1) << 3)) * RPITCH
                            + (uint32_t)((lane >> 4) << 4);

    // ---- staging index: each thread owns column cc (float4) of rows rbase+16j ----
    const int rbase = tid >> 4;
    const int cc    = tid & 15;

    // ---- stage Q (fp32 -> fp16, coalesced, conflict-free) ----
    #pragma unroll
    for (int j = 0; j < 8; j++) {
        int row = rbase + 16 * j;
        float4 f = *(const float4*)(qb + (size_t)(m0 + row) * Dh + cc * 4);
        *(uint2*)(smc + SM_Q + row * RPITCH + cc * 8) =
            make_uint2(ph2(f.x, f.y), ph2(f.z, f.w));
    }
    // ---- stage K/V tile 0 into buffer 0 ----
    #pragma unroll
    for (int j = 0; j < 4; j++) {
        int row = rbase + 16 * j;
        float4 fk = *(const float4*)(kb + (size_t)row * Dh + cc * 4);
        float4 fv = *(const float4*)(vb + (size_t)row * Dh + cc * 4);
        *(uint2*)(smc + SM_K0 + row * RPITCH + cc * 8) =
            make_uint2(ph2(fk.x, fk.y), ph2(fk.z, fk.w));
        *(uint2*)(smc + SM_V0 + row * RPITCH + cc * 8) =
            make_uint2(ph2(fv.x, fv.y), ph2(fv.z, fv.w));
    }
    __syncthreads();

    float o[8][4];
    #pragma unroll
    for (int d = 0; d < 8; d++)
        #pragma unroll
        for (int r = 0; r < 4; r++) o[d][r] = 0.f;
    float rs0 = 0.f, rs1 = 0.f;

    for (int tt = 0; tt < NTILES; tt++) {
        const uint32_t kbase = sb + ((tt & 1) ? SM_K1 : SM_K0);
        const uint32_t vbase = sb + ((tt & 1) ? SM_V1 : SM_V0);
        const bool pf = (tt < NTILES - 1);

        // ---- prefetch next K/V tile into registers (consumed at loop end) ----
        float4 kf[4], vf[4];
        if (pf) {
            const size_t nb = (size_t)(tt + 1) * BN;
            #pragma unroll
            for (int j = 0; j < 4; j++) {
                int row = rbase + 16 * j;
                kf[j] = *(const float4*)(kb + (nb + row) * Dh + cc * 4);
                vf[j] = *(const float4*)(vb + (nb + row) * Dh + cc * 4);
            }
        }

        // ---- S = Q K^T : 4 k-steps, 8 n-tiles ----
        float c[8][4];
        #pragma unroll
        for (int nf = 0; nf < 8; nf++)
            #pragma unroll
            for (int r = 0; r < 4; r++) c[nf][r] = 0.f;

        #pragma unroll
        for (int ks = 0; ks < 4; ks++) {
            uint32_t a[4];
            ldm_x4(a, qaddr + ks * 32);
            #pragma unroll
            for (int p = 0; p < 4; p++) {
                uint32_t b[4];
                ldm_x4(b, kbase + p * (16 * RPITCH) + ks * 32 + krow_off);
                mma16(c[2 * p],     a, b[0], b[1]);
                mma16(c[2 * p + 1], a, b[2], b[3]);
            }
        }

        // ---- poly + relu + rowsum (pre-rounded fp32) + in-register repack ----
        uint32_t ap[4][4];
        #pragma unroll
        for (int nf = 0; nf < 8; nf++) {
            float p0 = fmaxf(fmaf(fmaf(a2c, c[nf][0], b1c), c[nf][0], g0c), 0.f);
            float p1 = fmaxf(fmaf(fmaf(a2c, c[nf][1], b1c), c[nf][1], g0c), 0.f);
            float p2 = fmaxf(fmaf(fmaf(a2c, c[nf][2], b1c), c[nf][2], g0c), 0.f);
            float p3 = fmaxf(fmaf(fmaf(a2c, c[nf][3], b1c), c[nf][3], g0c), 0.f);
            rs0 += p0 + p1;
            rs1 += p2 + p3;
            ap[nf >> 1][(nf & 1) * 2 + 0] = ph2(p0, p1);
            ap[nf >> 1][(nf & 1) * 2 + 1] = ph2(p2, p3);
        }

        // ---- O += attn @ V : A from registers, B via ldmatrix.trans ----
        #pragma unroll
        for (int ks2 = 0; ks2 < 4; ks2++) {
            #pragma unroll
            for (int p = 0; p < 4; p++) {
                uint32_t b[4];
                ldm_x4t(b, vbase + ks2 * (16 * RPITCH) + p * 32 + vrow_off);
                mma16(o[2 * p],     ap[ks2], b[0], b[1]);
                mma16(o[2 * p + 1], ap[ks2], b[2], b[3]);
            }
        }

        // ---- store prefetched tile into the other buffer ----
        if (pf) {
            char* kd = smc + (((tt & 1) ? SM_K0 : SM_K1));
            char* vd = smc + (((tt & 1) ? SM_V0 : SM_V1));
            #pragma unroll
            for (int j = 0; j < 4; j++) {
                int row = rbase + 16 * j;
                *(uint2*)(kd + row * RPITCH + cc * 8) =
                    make_uint2(ph2(kf[j].x, kf[j].y), ph2(kf[j].z, kf[j].w));
                *(uint2*)(vd + row * RPITCH + cc * 8) =
                    make_uint2(ph2(vf[j].x, vf[j].y), ph2(vf[j].z, vf[j].w));
            }
            __syncthreads();
        }
    }

    // ---- rowsum closes within the warp: sum over the 4 t-lanes ----
    rs0 += __shfl_xor_sync(0xFFFFFFFFu, rs0, 1);
    rs0 += __shfl_xor_sync(0xFFFFFFFFu, rs0, 2);
    rs1 += __shfl_xor_sync(0xFFFFFFFFu, rs1, 1);
    rs1 += __shfl_xor_sync(0xFFFFFFFFu, rs1, 2);
    const float inv0 = 1.f / (rs0 + EPS);
    const float inv1 = 1.f / (rs1 + EPS);

    // ---- normalize + store ----
    const int row0 = m0 + w * 16 + g;
    #pragma unroll
    for (int d = 0; d < 8; d++) {
        float2 lo = {o[d][0] * inv0, o[d][1] * inv0};
        float2 hi = {o[d][2] * inv1, o[d][3] * inv1};
        *(float2*)(ob + (size_t)row0 * Dh + d * 8 + 2 * t)       = lo;
        *(float2*)(ob + (size_t)(row0 + 8) * Dh + d * 8 + 2 * t) = hi;
    }
}

extern "C" void kernel_launch(void* const* d_in, const int* in_sizes, int n_in,
                              void* d_out, int out_size)
{
    const float* q     = (const float*)d_in[0];
    const float* k     = (const float*)d_in[1];
    const float* v     = (const float*)d_in[2];
    const float* alpha = (const float*)d_in[3];
    const float* beta  = (const float*)d_in[4];
    const float* gamma = (const float*)d_in[5];
    float* out = (float*)d_out;

    cudaFuncSetAttribute(l2q_h2_kernel,
                         cudaFuncAttributeMaxDynamicSharedMemorySize, SMEM_BYTES);

    dim3 grid(Nq / BM, Bsz * H);
    l2q_h2_kernel<<<grid, NT, SMEM_BYTES>>>(q, k, v, alpha, beta, gamma, out);
}

// round 17
// speedup vs baseline: 1.5579x; 1.0252x over previous
#include <cuda_runtime.h>
#include <cuda_fp16.h>
#include <stdint.h>

#define Bsz 8
#define H   12
#define Nq  1024
#define Dh  64
#define SCALE 0.125f
#define EPS 1e-6f

#define BM 128
#define BN 64
#define NT 256
#define NTILES (Nq / BN)   // 16
#define RPITCH 144          // bytes per smem row (72 halves: 64 data + 8 pad)

// smem byte offsets
#define SM_Q  0                       // 128 rows -> 18432 B
#define SM_K0 18432                   // 64 rows  -> 9216 B
#define SM_K1 (18432 + 9216)
#define SM_V0 36864
#define SM_V1 (36864 + 9216)
#define SMEM_BYTES 55296

__device__ __forceinline__ uint32_t s2u(const void* p) {
    uint32_t a;
    asm("{ .reg .u64 t; cvta.to.shared.u64 t, %1; cvt.u32.u64 %0, t; }" : "=r"(a) : "l"(p));
    return a;
}
__device__ __forceinline__ uint32_t ph2(float lo, float hi) {
    __half2 h = __floats2half2_rn(lo, hi);   // .x = lo, .y = hi
    return *(uint32_t*)&h;
}
__device__ __forceinline__ void ldm_x4(uint32_t r[4], uint32_t addr) {
    asm volatile("ldmatrix.sync.aligned.m8n8.x4.shared.b16 {%0,%1,%2,%3}, [%4];"
                 : "=r"(r[0]), "=r"(r[1]), "=r"(r[2]), "=r"(r[3]) : "r"(addr));
}
__device__ __forceinline__ void ldm_x4t(uint32_t r[4], uint32_t addr) {
    asm volatile("ldmatrix.sync.aligned.m8n8.x4.trans.shared.b16 {%0,%1,%2,%3}, [%4];"
                 : "=r"(r[0]), "=r"(r[1]), "=r"(r[2]), "=r"(r[3]) : "r"(addr));
}
__device__ __forceinline__ void mma16(float c[4], const uint32_t a[4],
                                      uint32_t b0, uint32_t b1) {
    asm volatile(
        "mma.sync.aligned.m16n8k16.row.col.f32.f16.f16.f32 "
        "{%0,%1,%2,%3},{%4,%5,%6,%7},{%8,%9},{%0,%1,%2,%3};\n"
        : "+f"(c[0]), "+f"(c[1]), "+f"(c[2]), "+f"(c[3])
        : "r"(a[0]), "r"(a[1]), "r"(a[2]), "r"(a[3]), "r"(b0), "r"(b1));
}

__global__ __launch_bounds__(NT, 2) void l2q_h2_kernel(
    const float* __restrict__ q, const float* __restrict__ k,
    const float* __restrict__ v, const float* __restrict__ alpha,
    const float* __restrict__ beta, const float* __restrict__ gamma,
    float* __restrict__ out)
{
    extern __shared__ char smc[];
    const uint32_t sb = s2u(smc);

    const int tid  = threadIdx.x;
    const int w    = tid >> 5;    // warp 0..7 -> rows w*16..w*16+15
    const int lane = tid & 31;
    const int g    = lane >> 2;
    const int t    = lane & 3;

    const int bh = blockIdx.y;
    const int h  = bh % H;
    const int m0 = blockIdx.x * BM;

    const float* qb = q + (size_t)bh * Nq * Dh;
    const float* kb = k + (size_t)bh * Nq * Dh;
    const float* vb = v + (size_t)bh * Nq * Dh;
    float*       ob = out + (size_t)bh * Nq * Dh;

    const float a2c = alpha[h] * SCALE * SCALE;
    const float b1c = beta[h] * SCALE;
    const float g0c = gamma[h];

    // ---- per-lane ldmatrix address offsets ----
    // A (Q, row-major): lanes 0-15 -> rows (lane&15), lanes 16-31 -> same rows, k+8
    const uint32_t qaddr = sb + SM_Q + (uint32_t)(w * 16 + (lane & 15)) * RPITCH
                         + (uint32_t)((lane >> 4) << 4);
    // B (K natural = col-major k x n): groups (rows p16+l,k0)(rows,k0+8)(rows+8,k0)(rows+8,k0+8)
    const uint32_t krow_off = (uint32_t)((lane & 7) + ((lane >> 4) << 3)) * RPITCH
                            + (uint32_t)(((lane >> 3) & 1) << 4);
    // B (V row-major, .trans): groups (k0,d0)(k0+8,d0)(k0,d0+8)(k0+8,d0+8); rows = keys
    const uint32_t vrow_off = (uint32_t)((lane & 7) + (((lane >> 3) & 1) << 3)) * RPITCH
                            + (uint32_t)((lane >> 4) << 4);

    // ---- staging index: each thread owns column c (float4) of rows rbase+16j ----
    const int rbase = tid >> 4;
    const int cc    = tid & 15;

    // ---- stage Q (fp32 -> fp16, coalesced, conflict-free) ----
    #pragma unroll
    for (int j = 0; j < 8; j++) {
        int row = rbase + 16 * j;
        float4 f = *(const float4*)(qb + (size_t)(m0 + row) * Dh + cc * 4);
        *(uint2*)(smc + SM_Q + row * RPITCH + cc * 8) =
            make_uint2(ph2(f.x, f.y), ph2(f.z, f.w));
    }
    // ---- stage K/V tile 0 into buffer 0 ----
    #pragma unroll
    for (int j = 0; j < 4; j++) {
        int row = rbase + 16 * j;
        float4 fk = *(const float4*)(kb + (size_t)row * Dh + cc * 4);
        float4 fv = *(const float4*)(vb + (size_t)row * Dh + cc * 4);
        *(uint2*)(smc + SM_K0 + row * RPITCH + cc * 8) =
            make_uint2(ph2(fk.x, fk.y), ph2(fk.z, fk.w));
        *(uint2*)(smc + SM_V0 + row * RPITCH + cc * 8) =
            make_uint2(ph2(fv.x, fv.y), ph2(fv.z, fv.w));
    }
    __syncthreads();

    float o[8][4];
    #pragma unroll
    for (int d = 0; d < 8; d++)
        #pragma unroll
        for (int r = 0; r < 4; r++) o[d][r] = 0.f;
    float rs0 = 0.f, rs1 = 0.f;

    for (int tt = 0; tt < NTILES; tt++) {
        const uint32_t kbase = sb + ((tt & 1) ? SM_K1 : SM_K0);
        const uint32_t vbase = sb + ((tt & 1) ? SM_V1 : SM_V0);

        // ---- prefetch next K/V tile into registers (consumed at loop end) ----
        float4 kf[4], vf[4];
        if (tt < NTILES - 1) {
            const size_t nb = (size_t)(tt + 1) * BN;
            #pragma unroll
            for (int j = 0; j < 4; j++) {
                int row = rbase + 16 * j;
                kf[j] = *(const float4*)(kb + (nb + row) * Dh + cc * 4);
                vf[j] = *(const float4*)(vb + (nb + row) * Dh + cc * 4);
            }
        }

        // ---- S = Q K^T : 4 k-steps, 8 n-tiles ----
        float c[8][4];
        #pragma unroll
        for (int nf = 0; nf < 8; nf++)
            #pragma unroll
            for (int r = 0; r < 4; r++) c[nf][r] = 0.f;

        #pragma unroll
        for (int ks = 0; ks < 4; ks++) {
            uint32_t a[4];
            ldm_x4(a, qaddr + ks * 32);
            #pragma unroll
            for (int p = 0; p < 4; p++) {
                uint32_t b[4];
                ldm_x4(b, kbase + p * (16 * RPITCH) + ks * 32 + krow_off);
                mma16(c[2 * p],     a, b[0], b[1]);
                mma16(c[2 * p + 1], a, b[2], b[3]);
            }
        }

        // ---- poly + relu + rowsum + in-register repack to A-fragments ----
        uint32_t ap[4][4];
        #pragma unroll
        for (int nf = 0; nf < 8; nf++) {
            float p0 = fmaxf(fmaf(fmaf(a2c, c[nf][0], b1c), c[nf][0], g0c), 0.f);
            float p1 = fmaxf(fmaf(fmaf(a2c, c[nf][1], b1c), c[nf][1], g0c), 0.f);
            float p2 = fmaxf(fmaf(fmaf(a2c, c[nf][2], b1c), c[nf][2], g0c), 0.f);
            float p3 = fmaxf(fmaf(fmaf(a2c, c[nf][3], b1c), c[nf][3], g0c), 0.f);
            uint32_t u01 = ph2(p0, p1);
            uint32_t u23 = ph2(p2, p3);
            // rowsum uses the SAME fp16-rounded values the O-GEMM consumes
            __half2 h01 = *(__half2*)&u01, h23 = *(__half2*)&u23;
            float2 f01 = __half22float2(h01), f23 = __half22float2(h23);
            rs0 += f01.x + f01.y;
            rs1 += f23.x + f23.y;
            ap[nf >> 1][(nf & 1) * 2 + 0] = u01;
            ap[nf >> 1][(nf & 1) * 2 + 1] = u23;
        }

        // ---- O += attn @ V : A from registers, B via ldmatrix.trans ----
        #pragma unroll
        for (int ks2 = 0; ks2 < 4; ks2++) {
            #pragma unroll
            for (int p = 0; p < 4; p++) {
                uint32_t b[4];
                ldm_x4t(b, vbase + ks2 * (16 * RPITCH) + p * 32 + vrow_off);
                mma16(o[2 * p],     ap[ks2], b[0], b[1]);
                mma16(o[2 * p + 1], ap[ks2], b[2], b[3]);
            }
        }

        // ---- store prefetched tile into the other buffer ----
        if (tt < NTILES - 1) {
            char* kd = smc + (((tt & 1) ? SM_K0 : SM_K1));
            char* vd = smc + (((tt & 1) ? SM_V0 : SM_V1));
            #pragma unroll
            for (int j = 0; j < 4; j++) {
                int row = rbase + 16 * j;
                *(uint2*)(kd + row * RPITCH + cc * 8) =
                    make_uint2(ph2(kf[j].x, kf[j].y), ph2(kf[j].z, kf[j].w));
                *(uint2*)(vd + row * RPITCH + cc * 8) =
                    make_uint2(ph2(vf[j].x, vf[j].y), ph2(vf[j].z, vf[j].w));
            }
            __syncthreads();
        }
    }

    // ---- rowsum closes within the warp: sum over the 4 t-lanes ----
    rs0 += __shfl_xor_sync(0xFFFFFFFFu, rs0, 1);
    rs0 += __shfl_xor_sync(0xFFFFFFFFu, rs0, 2);
    rs1 += __shfl_xor_sync(0xFFFFFFFFu, rs1, 1);
    rs1 += __shfl_xor_sync(0xFFFFFFFFu, rs1, 2);
    const float inv0 = 1.f / (rs0 + EPS);
    const float inv1 = 1.f / (rs1 + EPS);

    // ---- normalize + store ----
    const int row0 = m0 + w * 16 + g;
    #pragma unroll
    for (int d = 0; d < 8; d++) {
        float2 lo = {o[d][0] * inv0, o[d][1] * inv0};
        float2 hi = {o[d][2] * inv1, o[d][3] * inv1};
        *(float2*)(ob + (size_t)row0 * Dh + d * 8 + 2 * t)       = lo;
        *(float2*)(ob + (size_t)(row0 + 8) * Dh + d * 8 + 2 * t) = hi;
    }
}

extern "C" void kernel_launch(void* const* d_in, const int* in_sizes, int n_in,
                              void* d_out, int out_size)
{
    const float* q     = (const float*)d_in[0];
    const float* k     = (const float*)d_in[1];
    const float* v     = (const float*)d_in[2];
    const float* alpha = (const float*)d_in[3];
    const float* beta  = (const float*)d_in[4];
    const float* gamma = (const float*)d_in[5];
    float* out = (float*)d_out;

    cudaFuncSetAttribute(l2q_h2_kernel,
                         cudaFuncAttributeMaxDynamicSharedMemorySize, SMEM_BYTES);

    dim3 grid(Nq / BM, Bsz * H);
    l2q_h2_kernel<<<grid, NT, SMEM_BYTES>>>(q, k, v, alpha, beta, gamma, out);
}